// round 16
// baseline (speedup 1.0000x reference)
#include <cuda_runtime.h>
#include <math.h>
#include <stdint.h>

// CRF loss: L=512 seq, B=512 batch, T=128 tags.
#define LL 512
#define BB 512
#define TT 128
#define NBC 2             // batches per CTA
#define NCTA (BB/NBC)     // 256 CTAs -> 2 CTAs/SM
#define NTHREADS 256
#define QJ 20             // padded j-eighth stride (words): jo*20 mod 32 covers all bank quads
#define PBROW (8*QJ)      // padded per-batch alpha row = 160 floats
#define LN2F 0.6931471805599453f

__device__ float g_logZ[BB];
__device__ float g_num[BB];

union F4U { float4 v; struct { unsigned long long p01, p23; } u; };

__device__ __forceinline__ unsigned long long ffma2(unsigned long long a,
                                                    unsigned long long b,
                                                    unsigned long long c) {
    unsigned long long d;
    asm("fma.rn.f32x2 %0, %1, %2, %3;" : "=l"(d) : "l"(a), "l"(b), "l"(c));
    return d;
}
__device__ __forceinline__ unsigned long long packf2(float lo, float hi) {
    unsigned long long r;
    asm("mov.b64 %0, {%1,%2};" : "=l"(r) : "f"(lo), "f"(hi));
    return r;
}
__device__ __forceinline__ float2 unpackf2(unsigned long long v) {
    float2 f;
    asm("mov.b64 {%0,%1}, %2;" : "=f"(f.x), "=f"(f.y) : "l"(v));
    return f;
}

// Org: 8 warps, 2 batches/CTA, 2 CTAs/SM. Lane: jo = lane>>2 (j-eighth, 16 j),
// kidx = lane&3, k0 = w*16 + kidx*4. Tile: 16j x 4k x 2b = 128 MACs = 64 FFMA2,
// but only 8 LDS.128/warp/step (half of R15). E: 32 u64 regs. Reduce: value-
// steered 7-shfl tree (4+2+1); lane finalizes (ab = lane>>4 &1,
// myk = k0 + 2*sel1 + sel2).
__global__ __launch_bounds__(NTHREADS, 2)
void crf_forward(const float* __restrict__ emissions,
                 const int* __restrict__ mask,
                 const float* __restrict__ start_t,
                 const float* __restrict__ end_t,
                 const float* __restrict__ trans)
{
    __shared__ __align__(16) float sPA[NBC * PBROW];   // ping
    __shared__ __align__(16) float sPB[NBC * PBROW];   // pong
    __shared__ __align__(16) float sZf[NBC][TT];
    __shared__ int sEa[NBC];

    const int tid  = threadIdx.x;
    const int w    = tid >> 5;
    const int lane = tid & 31;
    const int jo   = lane >> 2;          // j-eighth 0..7
    const int kidx = lane & 3;
    const int k0   = w * 16 + kidx * 4;  // lane's 4 k columns
    const int sel1 = (lane >> 2) & 1;    // jo bit0
    const int sel2 = (lane >> 3) & 1;    // jo bit1
    const int ab   = (lane >> 4) & 1;    // jo bit2 = assigned local batch
    const int myk  = k0 + sel1 * 2 + sel2;
    const int gba  = blockIdx.x * NBC + ab;
    const int ka   = ab * PBROW + (myk >> 4) * QJ + (myk & 15);
    const int jb   = jo * QJ;            // lane's j-eighth offset within a row
    const int ebase = ab * PBROW;        // p'[b][0] address (k=0 -> offset 0)

    // ---- E: 16 j x 4 k per lane, register-resident (32 u64) ----
    unsigned long long eR[4][2][4];      // [t][j-subpair][k col]
    #pragma unroll
    for (int t = 0; t < 4; ++t) {
        #pragma unroll
        for (int sub = 0; sub < 2; ++sub) {
            int j = jo * 16 + t * 4 + sub * 2;
            #pragma unroll
            for (int kc = 0; kc < 4; ++kc)
                eR[t][sub][kc] = packf2(__expf(trans[j * TT + k0 + kc]),
                                        __expf(trans[(j + 1) * TT + k0 + kc]));
        }
    }

    // ---- init: p~0[ab][myk], kept in register (256 lanes cover 2x128) ----
    float myp = __expf(start_t[myk] + emissions[(size_t)gba * TT + myk]);
    sPA[ka] = myp;
    __syncthreads();

    int e_acc = 0;

    // 2-deep emission/mask prefetch pipeline (pointer-increment only)
    const size_t ESTRIDE = (size_t)BB * TT;
    const float* ep = emissions + ((size_t)2 * BB + gba) * TT + myk;  // -> step 2
    const int*   mp = mask + 2 * BB + gba;
    float em_c = __ldcs(emissions + ((size_t)1 * BB + gba) * TT + myk);  // step 1
    int   m_c  = mask[1 * BB + gba];
    float em_n = __ldcs(ep);                                             // step 2
    int   m_n  = *mp;
    float xq_c = __expf(em_c);            // exp(emission) for the CURRENT step

    // ---- one step: Pin -> Pout; PF=1 while steps remain to prefetch ----
    #define STEP(Pin, Pout, PF)                                                 \
    {                                                                            \
        unsigned int pe = *(const unsigned int*)&(Pin)[ebase];  /* p'[b][0] */   \
        float scale = __int_as_float(0x7E800000 - (int)(pe & 0x7F800000u));      \
        float factor = xq_c * scale;                                             \
        int   es = (int)((pe >> 23) & 255u) - 126;                               \
        float xq_n = __expf(em_n);        /* next step's exp, off-chain */       \
        float em_f = 0.f; int m_f = 0;                                           \
        if (PF) { ep += ESTRIDE; mp += BB; em_f = __ldcs(ep); m_f = *mp; }       \
        unsigned long long ac0[4] = {0,0,0,0};  /* batch0, k cols 0..3 */        \
        unsigned long long ac1[4] = {0,0,0,0};  /* batch1 */                     \
        _Pragma("unroll")                                                        \
        for (int t = 0; t < 4; ++t) {                                            \
            F4U p0; p0.v = *(const float4*)((Pin) + jb + 4 * t);                 \
            F4U p1; p1.v = *(const float4*)((Pin) + PBROW + jb + 4 * t);         \
            _Pragma("unroll")                                                    \
            for (int kc = 0; kc < 4; ++kc) {                                     \
                ac0[kc] = ffma2(p0.u.p01, eR[t][0][kc], ac0[kc]);                \
                ac0[kc] = ffma2(p0.u.p23, eR[t][1][kc], ac0[kc]);                \
                ac1[kc] = ffma2(p1.u.p01, eR[t][0][kc], ac1[kc]);                \
                ac1[kc] = ffma2(p1.u.p23, eR[t][1][kc], ac1[kc]);                \
            }                                                                    \
        }                                                                        \
        float f0[4], f1[4];                                                      \
        _Pragma("unroll")                                                        \
        for (int kc = 0; kc < 4; ++kc) {                                         \
            float2 h0 = unpackf2(ac0[kc]); f0[kc] = h0.x + h0.y;                 \
            float2 h1 = unpackf2(ac1[kc]); f1[kc] = h1.x + h1.y;                 \
        }                                                                        \
        /* L1 (^4, jo bit0): keep 2 k, receive the other 2 */                    \
        float s0a = sel1 ? f0[0] : f0[2];                                        \
        float s0b = sel1 ? f0[1] : f0[3];                                        \
        float s1a = sel1 ? f1[0] : f1[2];                                        \
        float s1b = sel1 ? f1[1] : f1[3];                                        \
        float g0a = (sel1 ? f0[2] : f0[0]) + __shfl_xor_sync(0xffffffffu, s0a, 4);\
        float g0b = (sel1 ? f0[3] : f0[1]) + __shfl_xor_sync(0xffffffffu, s0b, 4);\
        float g1a = (sel1 ? f1[2] : f1[0]) + __shfl_xor_sync(0xffffffffu, s1a, 4);\
        float g1b = (sel1 ? f1[3] : f1[1]) + __shfl_xor_sync(0xffffffffu, s1b, 4);\
        /* L2 (^8, jo bit1): keep 1 k */                                         \
        float t0 = sel2 ? g0a : g0b;                                             \
        float t1 = sel2 ? g1a : g1b;                                             \
        float h0v = (sel2 ? g0b : g0a) + __shfl_xor_sync(0xffffffffu, t0, 8);    \
        float h1v = (sel2 ? g1b : g1a) + __shfl_xor_sync(0xffffffffu, t1, 8);    \
        /* L3 (^16, jo bit2): keep own batch */                                  \
        float t2 = ab ? h0v : h1v;                                               \
        float mine = (ab ? h1v : h0v) + __shfl_xor_sync(0xffffffffu, t2, 16);    \
        if (m_c) { myp = mine * factor; e_acc += es; }                           \
        (Pout)[ka] = myp;                                                        \
        em_c = em_n; m_c = m_n;                                                  \
        em_n = em_f; m_n = m_f;                                                  \
        xq_c = xq_n;                                                             \
        __syncthreads();                                                         \
    }

    // 511 steps. Prefetch runs through step 509 (loads for step 511);
    // the last two steps consume the pipeline without loading.
    for (int i = 0; i < 254; ++i) {
        STEP(sPA, sPB, 1);
        STEP(sPB, sPA, 1);
    }
    STEP(sPA, sPB, 1);   // step 509
    STEP(sPB, sPA, 0);   // step 510
    STEP(sPA, sPB, 0);   // step 511
    #undef STEP

    // ---- finalize: logZ = e_acc*ln2 + log( sum_k p~[k]*exp(end[k]) ) ----
    sZf[ab][myk] = myp * __expf(end_t[myk]);
    if (w == 0 && (lane == 0 || lane == 16)) sEa[ab] = e_acc;  // myk==0 owners
    __syncthreads();
    if (w == 0) {
        #pragma unroll
        for (int b = 0; b < NBC; ++b) {
            float v = sZf[b][lane] + sZf[b][lane + 32]
                    + sZf[b][lane + 64] + sZf[b][lane + 96];
            v += __shfl_xor_sync(0xffffffffu, v, 1);
            v += __shfl_xor_sync(0xffffffffu, v, 2);
            v += __shfl_xor_sync(0xffffffffu, v, 4);
            v += __shfl_xor_sync(0xffffffffu, v, 8);
            v += __shfl_xor_sync(0xffffffffu, v, 16);
            if (lane == 0)
                g_logZ[blockIdx.x * NBC + b] = (float)sEa[b] * LN2F + logf(v);
        }
    }
}

// Numerator: one block per batch.
__global__ void crf_num(const float* __restrict__ emissions,
                        const int*   __restrict__ tags,
                        const int*   __restrict__ mask,
                        const float* __restrict__ start_t,
                        const float* __restrict__ end_t,
                        const float* __restrict__ trans)
{
    const int b   = blockIdx.x;
    const int tid = threadIdx.x;
    __shared__ float rf[256];
    __shared__ int   ri[256];

    float loc = 0.f;
    int   cnt = 0;
    for (int i = tid; i < LL; i += 256) {
        int tag = tags[i * BB + b];
        int m   = mask[i * BB + b];
        if (m) {
            loc += emissions[((size_t)i * BB + b) * TT + tag];
            cnt++;
            if (i > 0) loc += trans[tags[(i - 1) * BB + b] * TT + tag];
        }
        if (i == 0) loc += start_t[tag];
    }
    rf[tid] = loc; ri[tid] = cnt;
    __syncthreads();
    #pragma unroll
    for (int s = 128; s > 0; s >>= 1) {
        if (tid < s) { rf[tid] += rf[tid + s]; ri[tid] += ri[tid + s]; }
        __syncthreads();
    }
    if (tid == 0) {
        int ends = ri[0] - 1;
        if (ends < 0) ends = 0;
        g_num[b] = rf[0] + end_t[tags[ends * BB + b]];
    }
}

__global__ void crf_final(float* __restrict__ out)
{
    __shared__ float r[512];
    const int tid = threadIdx.x;
    r[tid] = g_logZ[tid] - g_num[tid];
    __syncthreads();
    #pragma unroll
    for (int s = 256; s > 0; s >>= 1) {
        if (tid < s) r[tid] += r[tid + s];
        __syncthreads();
    }
    if (tid == 0) out[0] = r[0] * (1.0f / (float)BB);
}

extern "C" void kernel_launch(void* const* d_in, const int* in_sizes, int n_in,
                              void* d_out, int out_size)
{
    const float* emissions = (const float*)d_in[0];
    const int*   tags      = (const int*)d_in[1];
    const int*   mask      = (const int*)d_in[2];
    const float* start_t   = (const float*)d_in[3];
    const float* end_t     = (const float*)d_in[4];
    const float* trans     = (const float*)d_in[5];
    float*       out       = (float*)d_out;

    crf_forward<<<NCTA, NTHREADS>>>(emissions, mask, start_t, end_t, trans);
    crf_num<<<BB, 256>>>(emissions, tags, mask, start_t, end_t, trans);
    crf_final<<<1, BB>>>(out);
}

// round 17
// speedup vs baseline: 1.0574x; 1.0574x over previous
#include <cuda_runtime.h>
#include <math.h>
#include <stdint.h>

// CRF loss: L=512 seq, B=512 batch, T=128 tags.
#define LL 512
#define BB 512
#define TT 128
#define NBC 2             // batches per CTA
#define NCTA (BB/NBC)     // 256 CTAs -> 2 CTAs/SM
#define NTHREADS 256
#define PQ 36             // padded j-quarter stride (floats)
#define PB (4*PQ)         // padded per-batch alpha row = 144 floats
#define LN2F 0.6931471805599453f

__device__ float g_logZ[BB];
__device__ float g_num[BB];

union F4U { float4 v; struct { unsigned long long p01, p23; } u; };

__device__ __forceinline__ unsigned long long ffma2(unsigned long long a,
                                                    unsigned long long b,
                                                    unsigned long long c) {
    unsigned long long d;
    asm("fma.rn.f32x2 %0, %1, %2, %3;" : "=l"(d) : "l"(a), "l"(b), "l"(c));
    return d;
}
__device__ __forceinline__ unsigned long long packf2(float lo, float hi) {
    unsigned long long r;
    asm("mov.b64 %0, {%1,%2};" : "=l"(r) : "f"(lo), "f"(hi));
    return r;
}
__device__ __forceinline__ float2 unpackf2(unsigned long long v) {
    float2 f;
    asm("mov.b64 {%0,%1}, %2;" : "=f"(f.x), "=f"(f.y) : "l"(v));
    return f;
}

// Org (R15 champion, loop byte-identical): 8 warps, 2 batches/CTA, 2 CTAs/SM.
// Lane: jq=lane>>3 (j-quarter), kidx=lane&7, k0=w*16+kidx*2.
// Tile: 32j x 2k x 2b = 64 FFMA2/step. E: 32 u64 regs. Tail: 8-shfl tree.
// Scale: single-word bit math off p'[b][0]; exp(emission) pipelined 1 ahead;
// 2-deep __ldcs prefetch. NEW in R17: numerator folded into the prologue
// (warps 0-1), removing the separate crf_num kernel launch.
__global__ __launch_bounds__(NTHREADS, 2)
void crf_forward(const float* __restrict__ emissions,
                 const int* __restrict__ tags,
                 const int* __restrict__ mask,
                 const float* __restrict__ start_t,
                 const float* __restrict__ end_t,
                 const float* __restrict__ trans)
{
    __shared__ __align__(16) float sPA[NBC * PB];   // ping
    __shared__ __align__(16) float sPB[NBC * PB];   // pong
    __shared__ __align__(16) float sZf[NBC][TT];
    __shared__ int sEa[NBC];

    const int tid  = threadIdx.x;
    const int w    = tid >> 5;
    const int lane = tid & 31;
    const int jq   = lane >> 3;
    const int kidx = lane & 7;
    const int k0   = w * 16 + kidx * 2;
    const int ab   = jq & 1;             // assigned local batch
    const int ak   = jq >> 1;            // assigned k within pair
    const int myk  = k0 + ak;
    const int gba  = blockIdx.x * NBC + ab;
    const int ka   = ab * PB + (myk >> 5) * PQ + (myk & 31);  // addr of my element
    const int jb   = jq * PQ;            // lane's j-quarter offset within a row
    const int ebase = ab * PB;           // p'[b][0] address (scale estimate)

    // ---- folded numerator: warps 0-1 each handle one batch (one-time) ----
    if (w < 2) {
        const int b = blockIdx.x * NBC + w;
        float loc = 0.f;
        int   cnt = 0;
        #pragma unroll 4
        for (int t = 0; t < 16; ++t) {
            int i = lane + t * 32;
            int tag = tags[i * BB + b];
            int m   = mask[i * BB + b];
            if (m) {
                loc += emissions[((size_t)i * BB + b) * TT + tag];
                cnt++;
                if (i > 0) loc += trans[tags[(i - 1) * BB + b] * TT + tag];
            }
            if (i == 0) loc += start_t[tag];
        }
        #pragma unroll
        for (int off = 16; off; off >>= 1) {
            loc += __shfl_xor_sync(0xffffffffu, loc, off);
            cnt += __shfl_xor_sync(0xffffffffu, cnt, off);
        }
        if (lane == 0) {
            int ends = cnt - 1;
            if (ends < 0) ends = 0;
            g_num[b] = loc + end_t[tags[ends * BB + b]];
        }
    }

    // ---- E: 32 j x 2 k per lane, register-resident ----
    unsigned long long eR[8][2][2];
    #pragma unroll
    for (int t = 0; t < 8; ++t) {
        #pragma unroll
        for (int sub = 0; sub < 2; ++sub) {
            int j = jq * 32 + t * 4 + sub * 2;
            eR[t][sub][0] = packf2(__expf(trans[j * TT + k0]),
                                   __expf(trans[(j + 1) * TT + k0]));
            eR[t][sub][1] = packf2(__expf(trans[j * TT + k0 + 1]),
                                   __expf(trans[(j + 1) * TT + k0 + 1]));
        }
    }

    // ---- init: p~0[ab][myk], kept in register ----
    float myp = __expf(start_t[myk] + emissions[(size_t)gba * TT + myk]);
    sPA[ka] = myp;
    __syncthreads();

    int e_acc = 0;

    // 2-deep emission/mask prefetch pipeline (pointer-increment only)
    const size_t ESTRIDE = (size_t)BB * TT;
    const float* ep = emissions + ((size_t)2 * BB + gba) * TT + myk;  // -> step 2
    const int*   mp = mask + 2 * BB + gba;
    float em_c = __ldcs(emissions + ((size_t)1 * BB + gba) * TT + myk);  // step 1
    int   m_c  = mask[1 * BB + gba];
    float em_n = __ldcs(ep);                                             // step 2
    int   m_n  = *mp;
    float xq_c = __expf(em_c);            // exp(emission) for the CURRENT step

    // ---- one step: Pin -> Pout; PF=1 while steps remain to prefetch ----
    #define STEP(Pin, Pout, PF)                                                 \
    {                                                                            \
        unsigned int pe = *(const unsigned int*)&(Pin)[ebase];  /* p'[b][0] */   \
        float scale = __int_as_float(0x7E800000 - (int)(pe & 0x7F800000u));      \
        float factor = xq_c * scale;                                             \
        int   es = (int)((pe >> 23) & 255u) - 126;                               \
        float xq_n = __expf(em_n);        /* next step's exp, off-chain */       \
        float em_f = 0.f; int m_f = 0;                                           \
        if (PF) { ep += ESTRIDE; mp += BB; em_f = __ldcs(ep); m_f = *mp; }       \
        unsigned long long a00 = 0, a01 = 0, a10 = 0, a11 = 0;                   \
        _Pragma("unroll")                                                        \
        for (int t = 0; t < 8; ++t) {                                            \
            F4U p0; p0.v = *(const float4*)((Pin) + jb + 4 * t);                 \
            F4U p1; p1.v = *(const float4*)((Pin) + PB + jb + 4 * t);            \
            a00 = ffma2(p0.u.p01, eR[t][0][0], a00);                             \
            a01 = ffma2(p0.u.p01, eR[t][0][1], a01);                             \
            a10 = ffma2(p1.u.p01, eR[t][0][0], a10);                             \
            a11 = ffma2(p1.u.p01, eR[t][0][1], a11);                             \
            a00 = ffma2(p0.u.p23, eR[t][1][0], a00);                             \
            a01 = ffma2(p0.u.p23, eR[t][1][1], a01);                             \
            a10 = ffma2(p1.u.p23, eR[t][1][0], a10);                             \
            a11 = ffma2(p1.u.p23, eR[t][1][1], a11);                             \
        }                                                                        \
        float2 h;                                                                \
        h = unpackf2(a00); float f00 = h.x + h.y;                                \
        h = unpackf2(a01); float f01 = h.x + h.y;                                \
        h = unpackf2(a10); float f10 = h.x + h.y;                                \
        h = unpackf2(a11); float f11 = h.x + h.y;                                \
        f00 += __shfl_xor_sync(0xffffffffu, f00, 8);                             \
        f01 += __shfl_xor_sync(0xffffffffu, f01, 8);                             \
        f10 += __shfl_xor_sync(0xffffffffu, f10, 8);                             \
        f11 += __shfl_xor_sync(0xffffffffu, f11, 8);                             \
        f00 += __shfl_xor_sync(0xffffffffu, f00, 16);                            \
        f01 += __shfl_xor_sync(0xffffffffu, f01, 16);                            \
        f10 += __shfl_xor_sync(0xffffffffu, f10, 16);                            \
        f11 += __shfl_xor_sync(0xffffffffu, f11, 16);                            \
        float mine = ab ? (ak ? f11 : f10) : (ak ? f01 : f00);                   \
        if (m_c) { myp = mine * factor; e_acc += es; }                           \
        (Pout)[ka] = myp;                                                        \
        em_c = em_n; m_c = m_n;                                                  \
        em_n = em_f; m_n = m_f;                                                  \
        xq_c = xq_n;                                                             \
        __syncthreads();                                                         \
    }

    // 511 steps. Prefetch runs through step 509 (loads for step 511);
    // the last two steps consume the pipeline without loading.
    for (int i = 0; i < 254; ++i) {
        STEP(sPA, sPB, 1);
        STEP(sPB, sPA, 1);
    }
    STEP(sPA, sPB, 1);   // step 509
    STEP(sPB, sPA, 0);   // step 510
    STEP(sPA, sPB, 0);   // step 511
    #undef STEP

    // ---- finalize: logZ = e_acc*ln2 + log( sum_k p~[k]*exp(end[k]) ) ----
    sZf[ab][myk] = myp * __expf(end_t[myk]);
    if (w == 0 && kidx == 0 && ak == 0) sEa[ab] = e_acc;   // lanes 0 (ab=0), 8 (ab=1)
    __syncthreads();
    if (w == 0) {
        #pragma unroll
        for (int b = 0; b < NBC; ++b) {
            float v = sZf[b][lane] + sZf[b][lane + 32]
                    + sZf[b][lane + 64] + sZf[b][lane + 96];
            v += __shfl_xor_sync(0xffffffffu, v, 1);
            v += __shfl_xor_sync(0xffffffffu, v, 2);
            v += __shfl_xor_sync(0xffffffffu, v, 4);
            v += __shfl_xor_sync(0xffffffffu, v, 8);
            v += __shfl_xor_sync(0xffffffffu, v, 16);
            if (lane == 0)
                g_logZ[blockIdx.x * NBC + b] = (float)sEa[b] * LN2F + logf(v);
        }
    }
}

__global__ void crf_final(float* __restrict__ out)
{
    __shared__ float r[512];
    const int tid = threadIdx.x;
    r[tid] = g_logZ[tid] - g_num[tid];
    __syncthreads();
    #pragma unroll
    for (int s = 256; s > 0; s >>= 1) {
        if (tid < s) r[tid] += r[tid + s];
        __syncthreads();
    }
    if (tid == 0) out[0] = r[0] * (1.0f / (float)BB);
}

extern "C" void kernel_launch(void* const* d_in, const int* in_sizes, int n_in,
                              void* d_out, int out_size)
{
    const float* emissions = (const float*)d_in[0];
    const int*   tags      = (const int*)d_in[1];
    const int*   mask      = (const int*)d_in[2];
    const float* start_t   = (const float*)d_in[3];
    const float* end_t     = (const float*)d_in[4];
    const float* trans     = (const float*)d_in[5];
    float*       out       = (float*)d_out;

    crf_forward<<<NCTA, NTHREADS>>>(emissions, tags, mask, start_t, end_t, trans);
    crf_final<<<1, BB>>>(out);
}